// round 5
// baseline (speedup 1.0000x reference)
#include <cuda_runtime.h>

#define NN 100000
#define NE 1600000
#define CAP 128
#define NF1 128
#define NH  64
#define NC  40

typedef unsigned long long ull;

// -------- scratch (device globals; no allocation allowed) --------
__device__ float g_deg[NN];
__device__ int   g_cnt[NN];
__device__ int2  g_slot[(long long)NN * CAP];   // (src_row, float_bits(dinv[src]*w))
__device__ float g_h1[(long long)NN * NH];      // x @ W1
__device__ float g_out1[(long long)NN * NH];    // relu(aggregate + b1)
__device__ float g_h2[(long long)NN * NC];      // out1 @ W2

// -------- packed f32x2 helpers --------
__device__ __forceinline__ ull pack2(float x, float y) {
    ull r;
    asm("mov.b64 %0, {%1, %2};" : "=l"(r) : "f"(x), "f"(y));
    return r;
}
__device__ __forceinline__ void fma2(ull& d, ull a, ull b) {
    asm("fma.rn.f32x2 %0, %1, %2, %0;" : "+l"(d) : "l"(a), "l"(b));
}
__device__ __forceinline__ float2 unpack2(ull v) {
    float2 f;
    asm("mov.b64 {%0, %1}, %2;" : "=f"(f.x), "=f"(f.y) : "l"(v));
    return f;
}

// -------- prep kernels --------
__global__ void k_init() {
    int n = blockIdx.x * blockDim.x + threadIdx.x;
    if (n < NN) { g_deg[n] = 1.0f; g_cnt[n] = 0; }  // self-loop weight 1
}

__global__ void k_deg(const int* __restrict__ ei, const float* __restrict__ ew) {
    int e = blockIdx.x * blockDim.x + threadIdx.x;
    if (e < NE) {
        int c = ei[NE + e];
        if (c >= 0 && c < NN) atomicAdd(&g_deg[c], ew[e]);
    }
}

__global__ void k_place(const int* __restrict__ ei, const float* __restrict__ ew) {
    int e = blockIdx.x * blockDim.x + threadIdx.x;
    if (e >= NE) return;
    int r = ei[e];
    int c = ei[NE + e];
    if (r < 0 || r >= NN || c < 0 || c >= NN) return;
    float dr = rsqrtf(g_deg[r]);          // deg >= 1 always (self loop)
    float pnorm = dr * ew[e];             // dinv[c] factored out; applied in gather
    int pos = atomicAdd(&g_cnt[c], 1);
    if (pos < CAP) {
        int2 s;
        s.x = r;
        s.y = __float_as_int(pnorm);
        g_slot[(long long)c * CAP + pos] = s;
    }
}

// -------- GEMM1: g_h1[N,64] = x[N,128] @ W1[128,64] --------
// 128 threads, 64-row block, 4 rows x 8 cols per thread (f32x2 packed).
// sA stride 65 (odd): scalar A broadcast reads land on banks k+{0,4,8,12} -> 1 wf.
__global__ void gemm1(const float* __restrict__ A, const float* __restrict__ B) {
    __shared__ float sA[64][65];                  // [row][k], scalar-staged
    __shared__ __align__(16) float sB[64][68];    // [k][col]
    int tid = threadIdx.x;          // 0..127
    int tx = tid & 7;               // col group: cols tx*8 .. tx*8+7
    int ty = tid >> 3;              // row group: rows ty*4 .. ty*4+3
    int row0 = blockIdx.x * 64;
    ull acc2[4][4] = {};            // 4 rows x 8 cols (4 f32x2)

    for (int kc = 0; kc < 2; kc++) {
#pragma unroll
        for (int t = 0; t < 8; t++) {
            int lin = (t * 128 + tid) * 4;   // 0..4095
            int r  = lin >> 6;               // 0..63
            int k0 = lin & 63;
            int grow = row0 + r;
            float4 v = make_float4(0.f, 0.f, 0.f, 0.f);
            if (grow < NN) v = *(const float4*)&A[(long long)grow * NF1 + kc * 64 + k0];
            sA[r][k0 + 0] = v.x;
            sA[r][k0 + 1] = v.y;
            sA[r][k0 + 2] = v.z;
            sA[r][k0 + 3] = v.w;
            float4 w = *(const float4*)&B[(kc * 64 + r) * NH + k0];
            *(float4*)&sB[r][k0] = w;
        }
        __syncthreads();
#pragma unroll
        for (int k = 0; k < 64; k++) {
            float a0 = sA[ty * 4 + 0][k];
            float a1 = sA[ty * 4 + 1][k];
            float a2 = sA[ty * 4 + 2][k];
            float a3 = sA[ty * 4 + 3][k];
            ulonglong2 b0 = *(const ulonglong2*)&sB[k][tx * 8];
            ulonglong2 b1 = *(const ulonglong2*)&sB[k][tx * 8 + 4];
            ull p0 = pack2(a0, a0), p1 = pack2(a1, a1), p2 = pack2(a2, a2), p3 = pack2(a3, a3);
            fma2(acc2[0][0], p0, b0.x); fma2(acc2[0][1], p0, b0.y); fma2(acc2[0][2], p0, b1.x); fma2(acc2[0][3], p0, b1.y);
            fma2(acc2[1][0], p1, b0.x); fma2(acc2[1][1], p1, b0.y); fma2(acc2[1][2], p1, b1.x); fma2(acc2[1][3], p1, b1.y);
            fma2(acc2[2][0], p2, b0.x); fma2(acc2[2][1], p2, b0.y); fma2(acc2[2][2], p2, b1.x); fma2(acc2[2][3], p2, b1.y);
            fma2(acc2[3][0], p3, b0.x); fma2(acc2[3][1], p3, b0.y); fma2(acc2[3][2], p3, b1.x); fma2(acc2[3][3], p3, b1.y);
        }
        __syncthreads();
    }
#pragma unroll
    for (int i = 0; i < 4; i++) {
        int grow = row0 + ty * 4 + i;
        if (grow < NN) {
            float2 c0 = unpack2(acc2[i][0]);
            float2 c1 = unpack2(acc2[i][1]);
            float2 c2 = unpack2(acc2[i][2]);
            float2 c3 = unpack2(acc2[i][3]);
            float* o = &g_h1[(long long)grow * NH + tx * 8];
            *(float4*)&o[0] = make_float4(c0.x, c0.y, c1.x, c1.y);
            *(float4*)&o[4] = make_float4(c2.x, c2.y, c3.x, c3.y);
        }
    }
}

// -------- GEMM2: g_h2[N,40] = g_out1[N,64] @ W2[64,40] --------
// 160 threads (16 x 10), 64-row block, 4x4 register tile (f32x2), K=64.
__global__ void gemm2(const float* __restrict__ B) {
    __shared__ __align__(16) float sA[64][68];
    __shared__ __align__(16) float sB[64 * 40];
    int tid = threadIdx.x;           // 0..159
    int tx = tid % 10, ty = tid / 10;
    int row0 = blockIdx.x * 64;

    for (int idx = tid; idx < 1024; idx += 160) {   // 64 rows x 16 float4
        int r  = idx >> 4;
        int k0 = (idx & 15) << 2;
        int grow = row0 + r;
        float4 v = make_float4(0.f, 0.f, 0.f, 0.f);
        if (grow < NN) v = *(const float4*)&g_out1[(long long)grow * NH + k0];
        *(float4*)&sA[r][k0] = v;
    }
    for (int idx = tid; idx < 64 * 40; idx += 160) sB[idx] = B[idx];
    __syncthreads();

    ull acc2[4][2] = {};
#pragma unroll
    for (int k = 0; k < 64; k++) {
        const ull* bp = (const ull*)&sB[k * 40 + tx * 4];
        ull b01 = bp[0];
        ull b23 = bp[1];
#pragma unroll
        for (int i = 0; i < 4; i++) {
            float a = sA[ty * 4 + i][k];
            ull pa = pack2(a, a);
            fma2(acc2[i][0], pa, b01);
            fma2(acc2[i][1], pa, b23);
        }
    }
#pragma unroll
    for (int i = 0; i < 4; i++) {
        int grow = row0 + ty * 4 + i;
        if (grow < NN) {
            float2 lo = unpack2(acc2[i][0]);
            float2 hi = unpack2(acc2[i][1]);
            float4 v = make_float4(lo.x, lo.y, hi.x, hi.y);
            *(float4*)&g_h2[(long long)grow * NC + tx * 4] = v;
        }
    }
}

// -------- gather layer 1: warp per node, float2 lanes, paired slot loads --------
// out1[n][j] = relu(dc*(sum pnorm*h1[r][j] + dc*h1[n][j]) + b1[j]),  dc = dinv[n]
__global__ void gather1(const float* __restrict__ b1) {
    int node = blockIdx.x * 8 + (threadIdx.x >> 5);
    if (node >= NN) return;
    int lane = threadIdx.x & 31;
    float dc = rsqrtf(g_deg[node]);
    int c = min(g_cnt[node], CAP);
    const int2* slots = &g_slot[(long long)node * CAP];
    ull acc = 0;
    int k = 0;
    for (; k + 2 <= c; k += 2) {
        int4 s2 = *(const int4*)&slots[k];   // 16B aligned (k even, base 1024B aligned)
        float n0 = __int_as_float(s2.y);
        float n1 = __int_as_float(s2.w);
        ull h0 = *(const ull*)&g_h1[(long long)s2.x * NH + lane * 2];
        ull h1v = *(const ull*)&g_h1[(long long)s2.z * NH + lane * 2];
        fma2(acc, pack2(n0, n0), h0);
        fma2(acc, pack2(n1, n1), h1v);
    }
    if (k < c) {
        int2 s = slots[k];
        float nm = __int_as_float(s.y);
        ull h = *(const ull*)&g_h1[(long long)s.x * NH + lane * 2];
        fma2(acc, pack2(nm, nm), h);
    }
    float2 a = unpack2(acc);
    float2 self = *(const float2*)&g_h1[(long long)node * NH + lane * 2];
    float ox = fmaf(dc, fmaf(dc, self.x, a.x), __ldg(&b1[lane * 2]));
    float oy = fmaf(dc, fmaf(dc, self.y, a.y), __ldg(&b1[lane * 2 + 1]));
    float2 o = make_float2(fmaxf(ox, 0.f), fmaxf(oy, 0.f));
    *(float2*)&g_out1[(long long)node * NH + lane * 2] = o;
}

// -------- gather layer 2: warp per node, lanes 0..19 (float2), paired slots --------
__global__ void gather2(const float* __restrict__ b2, float* __restrict__ out) {
    int node = blockIdx.x * 8 + (threadIdx.x >> 5);
    if (node >= NN) return;
    int lane = threadIdx.x & 31;
    if (lane >= 20) return;
    float dc = rsqrtf(g_deg[node]);
    int c = min(g_cnt[node], CAP);
    const int2* slots = &g_slot[(long long)node * CAP];
    ull acc = 0;
    int k = 0;
    for (; k + 2 <= c; k += 2) {
        int4 s2 = *(const int4*)&slots[k];
        float n0 = __int_as_float(s2.y);
        float n1 = __int_as_float(s2.w);
        ull h0 = *(const ull*)&g_h2[(long long)s2.x * NC + lane * 2];
        ull h1v = *(const ull*)&g_h2[(long long)s2.z * NC + lane * 2];
        fma2(acc, pack2(n0, n0), h0);
        fma2(acc, pack2(n1, n1), h1v);
    }
    if (k < c) {
        int2 s = slots[k];
        float nm = __int_as_float(s.y);
        ull h = *(const ull*)&g_h2[(long long)s.x * NC + lane * 2];
        fma2(acc, pack2(nm, nm), h);
    }
    float2 a = unpack2(acc);
    float2 self = *(const float2*)&g_h2[(long long)node * NC + lane * 2];
    float2 o;
    o.x = fmaf(dc, fmaf(dc, self.x, a.x), __ldg(&b2[lane * 2]));
    o.y = fmaf(dc, fmaf(dc, self.y, a.y), __ldg(&b2[lane * 2 + 1]));
    *(float2*)&out[(long long)node * NC + lane * 2] = o;
}

extern "C" void kernel_launch(void* const* d_in, const int* in_sizes, int n_in,
                              void* d_out, int out_size) {
    const float* x  = (const float*)d_in[0];
    const int*   ei = (const int*)d_in[1];     // int32 (JAX default x64-disabled)
    const float* ew = (const float*)d_in[2];
    const float* W1 = (const float*)d_in[3];
    const float* b1 = (const float*)d_in[4];
    const float* W2 = (const float*)d_in[5];
    const float* b2 = (const float*)d_in[6];
    float* out = (float*)d_out;

    (void)in_sizes; (void)n_in; (void)out_size;

    k_init<<<(NN + 255) / 256, 256>>>();
    k_deg<<<(NE + 255) / 256, 256>>>(ei, ew);
    k_place<<<(NE + 255) / 256, 256>>>(ei, ew);

    gemm1<<<(NN + 63) / 64, 128>>>(x, W1);
    gather1<<<(NN + 7) / 8, 256>>>(b1);

    gemm2<<<(NN + 63) / 64, 160>>>(W2);
    gather2<<<(NN + 7) / 8, 256>>>(b2, out);
}

// round 6
// speedup vs baseline: 1.1724x; 1.1724x over previous
#include <cuda_runtime.h>

#define NN 100000
#define NE 1600000
#define CAP 128
#define NF1 128
#define NH  64
#define NC  40

typedef unsigned long long ull;

// -------- scratch (device globals; no allocation allowed) --------
__device__ float g_deg[NN];
__device__ int   g_cnt[NN];
__device__ int2  g_slot[(long long)NN * CAP];   // (src_row, float_bits(dinv[src]*w))
__device__ float g_h1[(long long)NN * NH];      // x @ W1
__device__ float g_out1[(long long)NN * NH];    // relu(aggregate + b1)
__device__ float g_h2[(long long)NN * NC];      // out1 @ W2

// -------- packed f32x2 helpers --------
__device__ __forceinline__ ull pack2(float x, float y) {
    ull r;
    asm("mov.b64 %0, {%1, %2};" : "=l"(r) : "f"(x), "f"(y));
    return r;
}
__device__ __forceinline__ void fma2(ull& d, ull a, ull b) {
    asm("fma.rn.f32x2 %0, %1, %2, %0;" : "+l"(d) : "l"(a), "l"(b));
}
__device__ __forceinline__ float2 unpack2(ull v) {
    float2 f;
    asm("mov.b64 {%0, %1}, %2;" : "=f"(f.x), "=f"(f.y) : "l"(v));
    return f;
}

// -------- prep kernels --------
__global__ void k_init() {
    int n = blockIdx.x * blockDim.x + threadIdx.x;
    if (n < NN) { g_deg[n] = 1.0f; g_cnt[n] = 0; }  // self-loop weight 1
}

__global__ void k_deg(const int* __restrict__ ei, const float* __restrict__ ew) {
    int e = blockIdx.x * blockDim.x + threadIdx.x;
    if (e < NE) {
        int c = ei[NE + e];
        if (c >= 0 && c < NN) atomicAdd(&g_deg[c], ew[e]);
    }
}

__global__ void k_place(const int* __restrict__ ei, const float* __restrict__ ew) {
    int e = blockIdx.x * blockDim.x + threadIdx.x;
    if (e >= NE) return;
    int r = ei[e];
    int c = ei[NE + e];
    if (r < 0 || r >= NN || c < 0 || c >= NN) return;
    float dr = rsqrtf(g_deg[r]);          // deg >= 1 always (self loop)
    float pnorm = dr * ew[e];             // dinv[c] factored out; applied in gather
    int pos = atomicAdd(&g_cnt[c], 1);
    if (pos < CAP) {
        int2 s;
        s.x = r;
        s.y = __float_as_int(pnorm);
        g_slot[(long long)c * CAP + pos] = s;
    }
}

// -------- GEMM1 (R3 config): g_h1[N,64] = x[N,128] @ W1[128,64] --------
// 256 threads, 64-row block, 4x4 register tile (f32x2 packed), K chunked by 64.
__global__ void gemm1(const float* __restrict__ A, const float* __restrict__ B) {
    __shared__ __align__(16) float sA[64][68];
    __shared__ __align__(16) float sB[64][64];
    int tid = threadIdx.x;
    int tx = tid & 15, ty = tid >> 4;
    int row0 = blockIdx.x * 64;
    ull acc2[4][2] = {};   // bits(0,0) == 0.0f pair

    for (int kc = 0; kc < 2; kc++) {
#pragma unroll
        for (int t = 0; t < 4; t++) {
            int lin = (t * 256 + tid) * 4;   // 0..4095
            int r  = lin >> 6;               // 0..63
            int k0 = lin & 63;
            int grow = row0 + r;
            float4 v = make_float4(0.f, 0.f, 0.f, 0.f);
            if (grow < NN) v = *(const float4*)&A[(long long)grow * NF1 + kc * 64 + k0];
            *(float4*)&sA[r][k0] = v;
            float4 w = *(const float4*)&B[(kc * 64 + r) * NH + k0];
            *(float4*)&sB[r][k0] = w;
        }
        __syncthreads();
#pragma unroll
        for (int k = 0; k < 64; k++) {
            const ull* bp = (const ull*)&sB[k][tx * 4];
            ull b01 = bp[0];
            ull b23 = bp[1];
#pragma unroll
            for (int i = 0; i < 4; i++) {
                float a = sA[ty * 4 + i][k];
                ull pa = pack2(a, a);
                fma2(acc2[i][0], pa, b01);
                fma2(acc2[i][1], pa, b23);
            }
        }
        __syncthreads();
    }
#pragma unroll
    for (int i = 0; i < 4; i++) {
        int grow = row0 + ty * 4 + i;
        if (grow < NN) {
            float2 lo = unpack2(acc2[i][0]);
            float2 hi = unpack2(acc2[i][1]);
            float4 v = make_float4(lo.x, lo.y, hi.x, hi.y);
            *(float4*)&g_h1[(long long)grow * NH + tx * 4] = v;
        }
    }
}

// -------- GEMM2: g_h2[N,40] = g_out1[N,64] @ W2[64,40] --------
// 160 threads (16 x 10), 64-row block, 4x4 register tile (f32x2), K=64.
__global__ void gemm2(const float* __restrict__ B) {
    __shared__ __align__(16) float sA[64][68];
    __shared__ __align__(16) float sB[64 * 40];
    int tid = threadIdx.x;           // 0..159
    int tx = tid % 10, ty = tid / 10;
    int row0 = blockIdx.x * 64;

    for (int idx = tid; idx < 1024; idx += 160) {   // 64 rows x 16 float4
        int r  = idx >> 4;
        int k0 = (idx & 15) << 2;
        int grow = row0 + r;
        float4 v = make_float4(0.f, 0.f, 0.f, 0.f);
        if (grow < NN) v = *(const float4*)&g_out1[(long long)grow * NH + k0];
        *(float4*)&sA[r][k0] = v;
    }
    for (int idx = tid; idx < 64 * 40; idx += 160) sB[idx] = B[idx];
    __syncthreads();

    ull acc2[4][2] = {};
#pragma unroll
    for (int k = 0; k < 64; k++) {
        const ull* bp = (const ull*)&sB[k * 40 + tx * 4];
        ull b01 = bp[0];
        ull b23 = bp[1];
#pragma unroll
        for (int i = 0; i < 4; i++) {
            float a = sA[ty * 4 + i][k];
            ull pa = pack2(a, a);
            fma2(acc2[i][0], pa, b01);
            fma2(acc2[i][1], pa, b23);
        }
    }
#pragma unroll
    for (int i = 0; i < 4; i++) {
        int grow = row0 + ty * 4 + i;
        if (grow < NN) {
            float2 lo = unpack2(acc2[i][0]);
            float2 hi = unpack2(acc2[i][1]);
            float4 v = make_float4(lo.x, lo.y, hi.x, hi.y);
            *(float4*)&g_h2[(long long)grow * NC + tx * 4] = v;
        }
    }
}

// -------- gather layer 1: warp per node, float2 lanes, paired slot loads --------
// out1[n][j] = relu(dc*(sum pnorm*h1[r][j] + dc*h1[n][j]) + b1[j]),  dc = dinv[n]
__global__ void gather1(const float* __restrict__ b1) {
    int node = blockIdx.x * 8 + (threadIdx.x >> 5);
    if (node >= NN) return;
    int lane = threadIdx.x & 31;
    float dc = rsqrtf(g_deg[node]);
    int c = min(g_cnt[node], CAP);
    const int2* slots = &g_slot[(long long)node * CAP];
    ull acc = 0;
    int k = 0;
    for (; k + 2 <= c; k += 2) {
        int4 s2 = *(const int4*)&slots[k];   // 16B aligned (k even, base 1024B aligned)
        float n0 = __int_as_float(s2.y);
        float n1 = __int_as_float(s2.w);
        ull h0 = *(const ull*)&g_h1[(long long)s2.x * NH + lane * 2];
        ull h1v = *(const ull*)&g_h1[(long long)s2.z * NH + lane * 2];
        fma2(acc, pack2(n0, n0), h0);
        fma2(acc, pack2(n1, n1), h1v);
    }
    if (k < c) {
        int2 s = slots[k];
        float nm = __int_as_float(s.y);
        ull h = *(const ull*)&g_h1[(long long)s.x * NH + lane * 2];
        fma2(acc, pack2(nm, nm), h);
    }
    float2 a = unpack2(acc);
    float2 self = *(const float2*)&g_h1[(long long)node * NH + lane * 2];
    float ox = fmaf(dc, fmaf(dc, self.x, a.x), __ldg(&b1[lane * 2]));
    float oy = fmaf(dc, fmaf(dc, self.y, a.y), __ldg(&b1[lane * 2 + 1]));
    float2 o = make_float2(fmaxf(ox, 0.f), fmaxf(oy, 0.f));
    *(float2*)&g_out1[(long long)node * NH + lane * 2] = o;
}

// -------- gather layer 2: warp per node, lanes 0..19 (float2), paired slots --------
__global__ void gather2(const float* __restrict__ b2, float* __restrict__ out) {
    int node = blockIdx.x * 8 + (threadIdx.x >> 5);
    if (node >= NN) return;
    int lane = threadIdx.x & 31;
    if (lane >= 20) return;
    float dc = rsqrtf(g_deg[node]);
    int c = min(g_cnt[node], CAP);
    const int2* slots = &g_slot[(long long)node * CAP];
    ull acc = 0;
    int k = 0;
    for (; k + 2 <= c; k += 2) {
        int4 s2 = *(const int4*)&slots[k];
        float n0 = __int_as_float(s2.y);
        float n1 = __int_as_float(s2.w);
        ull h0 = *(const ull*)&g_h2[(long long)s2.x * NC + lane * 2];
        ull h1v = *(const ull*)&g_h2[(long long)s2.z * NC + lane * 2];
        fma2(acc, pack2(n0, n0), h0);
        fma2(acc, pack2(n1, n1), h1v);
    }
    if (k < c) {
        int2 s = slots[k];
        float nm = __int_as_float(s.y);
        ull h = *(const ull*)&g_h2[(long long)s.x * NC + lane * 2];
        fma2(acc, pack2(nm, nm), h);
    }
    float2 a = unpack2(acc);
    float2 self = *(const float2*)&g_h2[(long long)node * NC + lane * 2];
    float2 o;
    o.x = fmaf(dc, fmaf(dc, self.x, a.x), __ldg(&b2[lane * 2]));
    o.y = fmaf(dc, fmaf(dc, self.y, a.y), __ldg(&b2[lane * 2 + 1]));
    *(float2*)&out[(long long)node * NC + lane * 2] = o;
}

extern "C" void kernel_launch(void* const* d_in, const int* in_sizes, int n_in,
                              void* d_out, int out_size) {
    const float* x  = (const float*)d_in[0];
    const int*   ei = (const int*)d_in[1];     // int32 (JAX default x64-disabled)
    const float* ew = (const float*)d_in[2];
    const float* W1 = (const float*)d_in[3];
    const float* b1 = (const float*)d_in[4];
    const float* W2 = (const float*)d_in[5];
    const float* b2 = (const float*)d_in[6];
    float* out = (float*)d_out;

    (void)in_sizes; (void)n_in; (void)out_size;

    // One-time stream/event creation (not device-memory allocation; identical
    // launch work every call). Fork/join pattern is graph-capture legal.
    static cudaStream_t s2 = nullptr;
    static cudaEvent_t eFork = nullptr, eJoin = nullptr;
    if (s2 == nullptr) {
        cudaStreamCreateWithFlags(&s2, cudaStreamNonBlocking);
        cudaEventCreateWithFlags(&eFork, cudaEventDisableTiming);
        cudaEventCreateWithFlags(&eJoin, cudaEventDisableTiming);
    }

    // Fork: gemm1 (x,W1 only) runs concurrently with edge preprocessing.
    cudaEventRecord(eFork, 0);
    cudaStreamWaitEvent(s2, eFork, 0);
    gemm1<<<(NN + 63) / 64, 256, 0, s2>>>(x, W1);
    cudaEventRecord(eJoin, s2);

    k_init<<<(NN + 255) / 256, 256>>>();
    k_deg<<<(NE + 255) / 256, 256>>>(ei, ew);
    k_place<<<(NE + 255) / 256, 256>>>(ei, ew);

    // Join: gather1 needs both gemm1 (h1) and k_place (slots).
    cudaStreamWaitEvent(0, eJoin, 0);
    gather1<<<(NN + 7) / 8, 256>>>(b1);

    gemm2<<<(NN + 63) / 64, 160>>>(W2);
    gather2<<<(NN + 7) / 8, 256>>>(b2, out);
}

// round 7
// speedup vs baseline: 1.2932x; 1.1030x over previous
#include <cuda_runtime.h>
#include <cuda_fp16.h>

#define NN 100000
#define NE 1600000
#define CAP 128
#define NF1 128
#define NH  64
#define NC  40

typedef unsigned long long ull;

// -------- scratch (device globals; no allocation allowed) --------
__device__ float  g_deg[NN];
__device__ int    g_cnt[NN];
__device__ int2   g_slot[(long long)NN * CAP];  // (src_row, float_bits(dinv[src]*w))
__device__ __half g_h1h[(long long)NN * NH];    // fp16(x @ W1)
__device__ float  g_out1[(long long)NN * NH];   // relu(aggregate + b1), fp32 for gemm2
__device__ __half g_h2h[(long long)NN * NC];    // fp16(out1 @ W2)

// -------- packed f32x2 helpers --------
__device__ __forceinline__ ull pack2(float x, float y) {
    ull r;
    asm("mov.b64 %0, {%1, %2};" : "=l"(r) : "f"(x), "f"(y));
    return r;
}
__device__ __forceinline__ void fma2(ull& d, ull a, ull b) {
    asm("fma.rn.f32x2 %0, %1, %2, %0;" : "+l"(d) : "l"(a), "l"(b));
}
__device__ __forceinline__ float2 unpack2(ull v) {
    float2 f;
    asm("mov.b64 {%0, %1}, %2;" : "=f"(f.x), "=f"(f.y) : "l"(v));
    return f;
}

// -------- prep kernels --------
__global__ void k_init() {
    int n = blockIdx.x * blockDim.x + threadIdx.x;
    if (n < NN) { g_deg[n] = 1.0f; g_cnt[n] = 0; }  // self-loop weight 1
}

__global__ void k_deg(const int* __restrict__ ei, const float* __restrict__ ew) {
    int e = blockIdx.x * blockDim.x + threadIdx.x;
    if (e < NE) {
        int c = ei[NE + e];
        if (c >= 0 && c < NN) atomicAdd(&g_deg[c], ew[e]);
    }
}

__global__ void k_place(const int* __restrict__ ei, const float* __restrict__ ew) {
    int e = blockIdx.x * blockDim.x + threadIdx.x;
    if (e >= NE) return;
    int r = ei[e];
    int c = ei[NE + e];
    if (r < 0 || r >= NN || c < 0 || c >= NN) return;
    float dr = rsqrtf(g_deg[r]);          // deg >= 1 always (self loop)
    float pnorm = dr * ew[e];             // dinv[c] factored out; applied in gather
    int pos = atomicAdd(&g_cnt[c], 1);
    if (pos < CAP) {
        int2 s;
        s.x = r;
        s.y = __float_as_int(pnorm);
        g_slot[(long long)c * CAP + pos] = s;
    }
}

// -------- GEMM1: g_h1h[N,64] = fp16(x[N,128] @ W1[128,64]) --------
// 256 threads, 64-row block, 4x4 register tile (f32x2 packed), K chunked by 64.
__global__ void gemm1(const float* __restrict__ A, const float* __restrict__ B) {
    __shared__ __align__(16) float sA[64][68];
    __shared__ __align__(16) float sB[64][64];
    int tid = threadIdx.x;
    int tx = tid & 15, ty = tid >> 4;
    int row0 = blockIdx.x * 64;
    ull acc2[4][2] = {};   // bits(0,0) == 0.0f pair

    for (int kc = 0; kc < 2; kc++) {
#pragma unroll
        for (int t = 0; t < 4; t++) {
            int lin = (t * 256 + tid) * 4;   // 0..4095
            int r  = lin >> 6;               // 0..63
            int k0 = lin & 63;
            int grow = row0 + r;
            float4 v = make_float4(0.f, 0.f, 0.f, 0.f);
            if (grow < NN) v = *(const float4*)&A[(long long)grow * NF1 + kc * 64 + k0];
            *(float4*)&sA[r][k0] = v;
            float4 w = *(const float4*)&B[(kc * 64 + r) * NH + k0];
            *(float4*)&sB[r][k0] = w;
        }
        __syncthreads();
#pragma unroll
        for (int k = 0; k < 64; k++) {
            const ull* bp = (const ull*)&sB[k][tx * 4];
            ull b01 = bp[0];
            ull b23 = bp[1];
#pragma unroll
            for (int i = 0; i < 4; i++) {
                float a = sA[ty * 4 + i][k];
                ull pa = pack2(a, a);
                fma2(acc2[i][0], pa, b01);
                fma2(acc2[i][1], pa, b23);
            }
        }
        __syncthreads();
    }
#pragma unroll
    for (int i = 0; i < 4; i++) {
        int grow = row0 + ty * 4 + i;
        if (grow < NN) {
            __half2 h0 = __float22half2_rn(unpack2(acc2[i][0]));
            __half2 h1 = __float22half2_rn(unpack2(acc2[i][1]));
            uint2 st;
            st.x = *(unsigned*)&h0;
            st.y = *(unsigned*)&h1;
            *(uint2*)&g_h1h[(long long)grow * NH + tx * 4] = st;   // 8B aligned
        }
    }
}

// -------- GEMM2: g_h2h[N,40] = fp16(g_out1[N,64] @ W2[64,40]) --------
// 160 threads (16 x 10), 64-row block, 4x4 register tile (f32x2), K=64.
__global__ void gemm2(const float* __restrict__ B) {
    __shared__ __align__(16) float sA[64][68];
    __shared__ __align__(16) float sB[64 * 40];
    int tid = threadIdx.x;           // 0..159
    int tx = tid % 10, ty = tid / 10;
    int row0 = blockIdx.x * 64;

    for (int idx = tid; idx < 1024; idx += 160) {   // 64 rows x 16 float4
        int r  = idx >> 4;
        int k0 = (idx & 15) << 2;
        int grow = row0 + r;
        float4 v = make_float4(0.f, 0.f, 0.f, 0.f);
        if (grow < NN) v = *(const float4*)&g_out1[(long long)grow * NH + k0];
        *(float4*)&sA[r][k0] = v;
    }
    for (int idx = tid; idx < 64 * 40; idx += 160) sB[idx] = B[idx];
    __syncthreads();

    ull acc2[4][2] = {};
#pragma unroll
    for (int k = 0; k < 64; k++) {
        const ull* bp = (const ull*)&sB[k * 40 + tx * 4];
        ull b01 = bp[0];
        ull b23 = bp[1];
#pragma unroll
        for (int i = 0; i < 4; i++) {
            float a = sA[ty * 4 + i][k];
            ull pa = pack2(a, a);
            fma2(acc2[i][0], pa, b01);
            fma2(acc2[i][1], pa, b23);
        }
    }
#pragma unroll
    for (int i = 0; i < 4; i++) {
        int grow = row0 + ty * 4 + i;
        if (grow < NN) {
            __half2 h0 = __float22half2_rn(unpack2(acc2[i][0]));
            __half2 h1 = __float22half2_rn(unpack2(acc2[i][1]));
            uint2 st;
            st.x = *(unsigned*)&h0;
            st.y = *(unsigned*)&h1;
            *(uint2*)&g_h2h[(long long)grow * NC + tx * 4] = st;   // 8B aligned
        }
    }
}

// -------- gather layer 1: warp per node, fp16 rows, 4-way slot unroll --------
// out1[n][j] = relu(dc*(sum pnorm*h1[r][j] + dc*h1[n][j]) + b1[j]),  dc = dinv[n]
__global__ void gather1(const float* __restrict__ b1) {
    int node = blockIdx.x * 8 + (threadIdx.x >> 5);
    if (node >= NN) return;
    int lane = threadIdx.x & 31;
    float dc = rsqrtf(g_deg[node]);
    int c = min(g_cnt[node], CAP);
    const int2* slots = &g_slot[(long long)node * CAP];
    float2 acc = make_float2(0.f, 0.f);
    int k = 0;
    for (; k + 4 <= c; k += 4) {
        int4 sA4 = *(const int4*)&slots[k];
        int4 sB4 = *(const int4*)&slots[k + 2];
        __half2 v0 = *(const __half2*)&g_h1h[(long long)sA4.x * NH + lane * 2];
        __half2 v1 = *(const __half2*)&g_h1h[(long long)sA4.z * NH + lane * 2];
        __half2 v2 = *(const __half2*)&g_h1h[(long long)sB4.x * NH + lane * 2];
        __half2 v3 = *(const __half2*)&g_h1h[(long long)sB4.z * NH + lane * 2];
        float n0 = __int_as_float(sA4.y), n1 = __int_as_float(sA4.w);
        float n2 = __int_as_float(sB4.y), n3 = __int_as_float(sB4.w);
        float2 f0 = __half22float2(v0), f1 = __half22float2(v1);
        float2 f2 = __half22float2(v2), f3 = __half22float2(v3);
        acc.x = fmaf(n0, f0.x, acc.x); acc.y = fmaf(n0, f0.y, acc.y);
        acc.x = fmaf(n1, f1.x, acc.x); acc.y = fmaf(n1, f1.y, acc.y);
        acc.x = fmaf(n2, f2.x, acc.x); acc.y = fmaf(n2, f2.y, acc.y);
        acc.x = fmaf(n3, f3.x, acc.x); acc.y = fmaf(n3, f3.y, acc.y);
    }
    for (; k < c; k++) {
        int2 s = slots[k];
        float nm = __int_as_float(s.y);
        float2 f = __half22float2(*(const __half2*)&g_h1h[(long long)s.x * NH + lane * 2]);
        acc.x = fmaf(nm, f.x, acc.x);
        acc.y = fmaf(nm, f.y, acc.y);
    }
    float2 self = __half22float2(*(const __half2*)&g_h1h[(long long)node * NH + lane * 2]);
    float ox = fmaf(dc, fmaf(dc, self.x, acc.x), __ldg(&b1[lane * 2]));
    float oy = fmaf(dc, fmaf(dc, self.y, acc.y), __ldg(&b1[lane * 2 + 1]));
    float2 o = make_float2(fmaxf(ox, 0.f), fmaxf(oy, 0.f));
    *(float2*)&g_out1[(long long)node * NH + lane * 2] = o;
}

// -------- gather layer 2: warp per node, lanes 0..19, fp16 rows, 4-way unroll --------
__global__ void gather2(const float* __restrict__ b2, float* __restrict__ out) {
    int node = blockIdx.x * 8 + (threadIdx.x >> 5);
    if (node >= NN) return;
    int lane = threadIdx.x & 31;
    if (lane >= 20) return;
    float dc = rsqrtf(g_deg[node]);
    int c = min(g_cnt[node], CAP);
    const int2* slots = &g_slot[(long long)node * CAP];
    float2 acc = make_float2(0.f, 0.f);
    int k = 0;
    for (; k + 4 <= c; k += 4) {
        int4 sA4 = *(const int4*)&slots[k];
        int4 sB4 = *(const int4*)&slots[k + 2];
        __half2 v0 = *(const __half2*)&g_h2h[(long long)sA4.x * NC + lane * 2];
        __half2 v1 = *(const __half2*)&g_h2h[(long long)sA4.z * NC + lane * 2];
        __half2 v2 = *(const __half2*)&g_h2h[(long long)sB4.x * NC + lane * 2];
        __half2 v3 = *(const __half2*)&g_h2h[(long long)sB4.z * NC + lane * 2];
        float n0 = __int_as_float(sA4.y), n1 = __int_as_float(sA4.w);
        float n2 = __int_as_float(sB4.y), n3 = __int_as_float(sB4.w);
        float2 f0 = __half22float2(v0), f1 = __half22float2(v1);
        float2 f2 = __half22float2(v2), f3 = __half22float2(v3);
        acc.x = fmaf(n0, f0.x, acc.x); acc.y = fmaf(n0, f0.y, acc.y);
        acc.x = fmaf(n1, f1.x, acc.x); acc.y = fmaf(n1, f1.y, acc.y);
        acc.x = fmaf(n2, f2.x, acc.x); acc.y = fmaf(n2, f2.y, acc.y);
        acc.x = fmaf(n3, f3.x, acc.x); acc.y = fmaf(n3, f3.y, acc.y);
    }
    for (; k < c; k++) {
        int2 s = slots[k];
        float nm = __int_as_float(s.y);
        float2 f = __half22float2(*(const __half2*)&g_h2h[(long long)s.x * NC + lane * 2]);
        acc.x = fmaf(nm, f.x, acc.x);
        acc.y = fmaf(nm, f.y, acc.y);
    }
    float2 self = __half22float2(*(const __half2*)&g_h2h[(long long)node * NC + lane * 2]);
    float2 o;
    o.x = fmaf(dc, fmaf(dc, self.x, acc.x), __ldg(&b2[lane * 2]));
    o.y = fmaf(dc, fmaf(dc, self.y, acc.y), __ldg(&b2[lane * 2 + 1]));
    *(float2*)&out[(long long)node * NC + lane * 2] = o;
}

extern "C" void kernel_launch(void* const* d_in, const int* in_sizes, int n_in,
                              void* d_out, int out_size) {
    const float* x  = (const float*)d_in[0];
    const int*   ei = (const int*)d_in[1];     // int32 (JAX default x64-disabled)
    const float* ew = (const float*)d_in[2];
    const float* W1 = (const float*)d_in[3];
    const float* b1 = (const float*)d_in[4];
    const float* W2 = (const float*)d_in[5];
    const float* b2 = (const float*)d_in[6];
    float* out = (float*)d_out;

    (void)in_sizes; (void)n_in; (void)out_size;

    static cudaStream_t s2 = nullptr;
    static cudaEvent_t eFork = nullptr, eJoin = nullptr;
    if (s2 == nullptr) {
        cudaStreamCreateWithFlags(&s2, cudaStreamNonBlocking);
        cudaEventCreateWithFlags(&eFork, cudaEventDisableTiming);
        cudaEventCreateWithFlags(&eJoin, cudaEventDisableTiming);
    }

    // Fork: gemm1 (x,W1 only) runs concurrently with edge preprocessing.
    cudaEventRecord(eFork, 0);
    cudaStreamWaitEvent(s2, eFork, 0);
    gemm1<<<(NN + 63) / 64, 256, 0, s2>>>(x, W1);
    cudaEventRecord(eJoin, s2);

    k_init<<<(NN + 255) / 256, 256>>>();
    k_deg<<<(NE + 255) / 256, 256>>>(ei, ew);
    k_place<<<(NE + 255) / 256, 256>>>(ei, ew);

    // Join: gather1 needs both gemm1 (h1) and k_place (slots).
    cudaStreamWaitEvent(0, eJoin, 0);
    gather1<<<(NN + 7) / 8, 256>>>(b1);

    gemm2<<<(NN + 63) / 64, 160>>>(W2);
    gather2<<<(NN + 7) / 8, 256>>>(b2, out);
}

// round 8
// speedup vs baseline: 1.3282x; 1.0271x over previous
#include <cuda_runtime.h>
#include <cuda_fp16.h>

#define NN 100000
#define NE 1600000
#define CAP 128
#define NF1 128
#define NH  64
#define NC  40

typedef unsigned long long ull;

// -------- scratch (device globals; no allocation allowed) --------
__device__ float  g_deg[NN];
__device__ int    g_cnt[NN];
__device__ int2   g_slot[(long long)NN * CAP];  // (src_row, float_bits(dinv[src]*w)); zero-init -> row 0 safe
__device__ __half g_h1h[(long long)NN * NH];    // fp16(x @ W1)
__device__ __half g_h2h[(long long)NN * NC];    // fp16(out1 @ W2)

// -------- packed f32x2 helpers --------
__device__ __forceinline__ ull pack2(float x, float y) {
    ull r;
    asm("mov.b64 %0, {%1, %2};" : "=l"(r) : "f"(x), "f"(y));
    return r;
}
__device__ __forceinline__ void fma2(ull& d, ull a, ull b) {
    asm("fma.rn.f32x2 %0, %1, %2, %0;" : "+l"(d) : "l"(a), "l"(b));
}
__device__ __forceinline__ float2 unpack2(ull v) {
    float2 f;
    asm("mov.b64 {%0, %1}, %2;" : "=f"(f.x), "=f"(f.y) : "l"(v));
    return f;
}

// -------- prep kernels --------
__global__ void k_init() {
    int n = blockIdx.x * blockDim.x + threadIdx.x;
    if (n < NN) { g_deg[n] = 1.0f; g_cnt[n] = 0; }  // self-loop weight 1
}

__global__ void k_deg(const int* __restrict__ ei, const float* __restrict__ ew) {
    int e = blockIdx.x * blockDim.x + threadIdx.x;
    if (e < NE) {
        int c = ei[NE + e];
        if (c >= 0 && c < NN) atomicAdd(&g_deg[c], ew[e]);
    }
}

__global__ void k_place(const int* __restrict__ ei, const float* __restrict__ ew) {
    int e = blockIdx.x * blockDim.x + threadIdx.x;
    if (e >= NE) return;
    int r = ei[e];
    int c = ei[NE + e];
    if (r < 0 || r >= NN || c < 0 || c >= NN) return;
    float dr = rsqrtf(g_deg[r]);          // deg >= 1 always (self loop)
    float pnorm = dr * ew[e];             // dinv[c] factored out; applied in gather
    int pos = atomicAdd(&g_cnt[c], 1);
    if (pos < CAP) {
        int2 s;
        s.x = r;
        s.y = __float_as_int(pnorm);
        g_slot[(long long)c * CAP + pos] = s;
    }
}

// -------- 8-way masked gather group: acc += masked pnorm * h[row][lane*2 .. +1] --------
// Always loads a full group of 8 slots (CAP-padded array, all rows valid);
// weights for kk+i >= c are forced to 0. No serial tail -> full MLP.
template<int STRIDE>
__device__ __forceinline__ float2 gather_rows(const int2* __restrict__ slots, int c,
                                              const __half* __restrict__ h, int lane) {
    float2 acc = make_float2(0.f, 0.f);
    for (int kk = 0; kk < c; kk += 8) {
        int4 sa = *(const int4*)&slots[kk];
        int4 sb = *(const int4*)&slots[kk + 2];
        int4 sc = *(const int4*)&slots[kk + 4];
        int4 sd = *(const int4*)&slots[kk + 6];
        __half2 v0 = *(const __half2*)&h[(long long)sa.x * STRIDE + lane * 2];
        __half2 v1 = *(const __half2*)&h[(long long)sa.z * STRIDE + lane * 2];
        __half2 v2 = *(const __half2*)&h[(long long)sb.x * STRIDE + lane * 2];
        __half2 v3 = *(const __half2*)&h[(long long)sb.z * STRIDE + lane * 2];
        __half2 v4 = *(const __half2*)&h[(long long)sc.x * STRIDE + lane * 2];
        __half2 v5 = *(const __half2*)&h[(long long)sc.z * STRIDE + lane * 2];
        __half2 v6 = *(const __half2*)&h[(long long)sd.x * STRIDE + lane * 2];
        __half2 v7 = *(const __half2*)&h[(long long)sd.z * STRIDE + lane * 2];
        float n0 = (kk + 0 < c) ? __int_as_float(sa.y) : 0.f;
        float n1 = (kk + 1 < c) ? __int_as_float(sa.w) : 0.f;
        float n2 = (kk + 2 < c) ? __int_as_float(sb.y) : 0.f;
        float n3 = (kk + 3 < c) ? __int_as_float(sb.w) : 0.f;
        float n4 = (kk + 4 < c) ? __int_as_float(sc.y) : 0.f;
        float n5 = (kk + 5 < c) ? __int_as_float(sc.w) : 0.f;
        float n6 = (kk + 6 < c) ? __int_as_float(sd.y) : 0.f;
        float n7 = (kk + 7 < c) ? __int_as_float(sd.w) : 0.f;
        float2 f0 = __half22float2(v0), f1 = __half22float2(v1);
        float2 f2 = __half22float2(v2), f3 = __half22float2(v3);
        float2 f4 = __half22float2(v4), f5 = __half22float2(v5);
        float2 f6 = __half22float2(v6), f7 = __half22float2(v7);
        acc.x = fmaf(n0, f0.x, acc.x); acc.y = fmaf(n0, f0.y, acc.y);
        acc.x = fmaf(n1, f1.x, acc.x); acc.y = fmaf(n1, f1.y, acc.y);
        acc.x = fmaf(n2, f2.x, acc.x); acc.y = fmaf(n2, f2.y, acc.y);
        acc.x = fmaf(n3, f3.x, acc.x); acc.y = fmaf(n3, f3.y, acc.y);
        acc.x = fmaf(n4, f4.x, acc.x); acc.y = fmaf(n4, f4.y, acc.y);
        acc.x = fmaf(n5, f5.x, acc.x); acc.y = fmaf(n5, f5.y, acc.y);
        acc.x = fmaf(n6, f6.x, acc.x); acc.y = fmaf(n6, f6.y, acc.y);
        acc.x = fmaf(n7, f7.x, acc.x); acc.y = fmaf(n7, f7.y, acc.y);
    }
    return acc;
}

// -------- GEMM1: g_h1h[N,64] = fp16(x[N,128] @ W1[128,64]) --------
// 256 threads, 64-row block, 4x4 register tile (f32x2 packed), K chunked by 64.
__global__ void gemm1(const float* __restrict__ A, const float* __restrict__ B) {
    __shared__ __align__(16) float sA[64][68];
    __shared__ __align__(16) float sB[64][64];
    int tid = threadIdx.x;
    int tx = tid & 15, ty = tid >> 4;
    int row0 = blockIdx.x * 64;
    ull acc2[4][2] = {};   // bits(0,0) == 0.0f pair

    for (int kc = 0; kc < 2; kc++) {
#pragma unroll
        for (int t = 0; t < 4; t++) {
            int lin = (t * 256 + tid) * 4;   // 0..4095
            int r  = lin >> 6;               // 0..63
            int k0 = lin & 63;
            int grow = row0 + r;
            float4 v = make_float4(0.f, 0.f, 0.f, 0.f);
            if (grow < NN) v = *(const float4*)&A[(long long)grow * NF1 + kc * 64 + k0];
            *(float4*)&sA[r][k0] = v;
            float4 w = *(const float4*)&B[(kc * 64 + r) * NH + k0];
            *(float4*)&sB[r][k0] = w;
        }
        __syncthreads();
#pragma unroll
        for (int k = 0; k < 64; k++) {
            const ull* bp = (const ull*)&sB[k][tx * 4];
            ull b01 = bp[0];
            ull b23 = bp[1];
#pragma unroll
            for (int i = 0; i < 4; i++) {
                float a = sA[ty * 4 + i][k];
                ull pa = pack2(a, a);
                fma2(acc2[i][0], pa, b01);
                fma2(acc2[i][1], pa, b23);
            }
        }
        __syncthreads();
    }
#pragma unroll
    for (int i = 0; i < 4; i++) {
        int grow = row0 + ty * 4 + i;
        if (grow < NN) {
            __half2 h0 = __float22half2_rn(unpack2(acc2[i][0]));
            __half2 h1 = __float22half2_rn(unpack2(acc2[i][1]));
            uint2 st;
            st.x = *(unsigned*)&h0;
            st.y = *(unsigned*)&h1;
            *(uint2*)&g_h1h[(long long)grow * NH + tx * 4] = st;   // 8B aligned
        }
    }
}

// -------- FUSED gather1 + GEMM2 --------
// Phase 1: 8 warps x 8 nodes -> out1 rows (bias+ReLU) straight into smem sA.
// Phase 2: 160 threads do g_h2h[64,40] = fp16(sA[64,64] @ W2[64,40]).
__global__ void g1g2(const float* __restrict__ b1, const float* __restrict__ W2) {
    __shared__ __align__(16) float sA[64][68];    // out1 rows (fp32)
    __shared__ __align__(16) float sB[64 * 40];   // W2
    int tid = threadIdx.x;          // 0..255
    int warp = tid >> 5, lane = tid & 31;
    int row0 = blockIdx.x * 64;

    for (int idx = tid; idx < 64 * 40; idx += 256) sB[idx] = W2[idx];

    float bx = __ldg(&b1[lane * 2]);
    float by = __ldg(&b1[lane * 2 + 1]);

    for (int i = 0; i < 8; i++) {
        int r = warp * 8 + i;
        int node = row0 + r;
        float2 o = make_float2(0.f, 0.f);
        if (node < NN) {
            float dc = rsqrtf(g_deg[node]);
            int c = min(g_cnt[node], CAP);
            float2 acc = gather_rows<NH>(&g_slot[(long long)node * CAP], c, g_h1h, lane);
            float2 self = __half22float2(*(const __half2*)&g_h1h[(long long)node * NH + lane * 2]);
            o.x = fmaxf(fmaf(dc, fmaf(dc, self.x, acc.x), bx), 0.f);
            o.y = fmaxf(fmaf(dc, fmaf(dc, self.y, acc.y), by), 0.f);
        }
        *(float2*)&sA[r][lane * 2] = o;
    }
    __syncthreads();

    if (tid < 160) {
        int tx = tid % 10, ty = tid / 10;
        ull acc2[4][2] = {};
#pragma unroll
        for (int k = 0; k < 64; k++) {
            const ull* bp = (const ull*)&sB[k * 40 + tx * 4];
            ull b01 = bp[0];
            ull b23 = bp[1];
#pragma unroll
            for (int i = 0; i < 4; i++) {
                float a = sA[ty * 4 + i][k];
                ull pa = pack2(a, a);
                fma2(acc2[i][0], pa, b01);
                fma2(acc2[i][1], pa, b23);
            }
        }
#pragma unroll
        for (int i = 0; i < 4; i++) {
            int grow = row0 + ty * 4 + i;
            if (grow < NN) {
                __half2 h0 = __float22half2_rn(unpack2(acc2[i][0]));
                __half2 h1 = __float22half2_rn(unpack2(acc2[i][1]));
                uint2 st;
                st.x = *(unsigned*)&h0;
                st.y = *(unsigned*)&h1;
                *(uint2*)&g_h2h[(long long)grow * NC + tx * 4] = st;   // 8B aligned
            }
        }
    }
}

// -------- gather layer 2: warp per node, lanes 0..19, 8-way masked groups --------
__global__ void gather2(const float* __restrict__ b2, float* __restrict__ out) {
    int node = blockIdx.x * 8 + (threadIdx.x >> 5);
    if (node >= NN) return;
    int lane = threadIdx.x & 31;
    if (lane >= 20) return;
    float dc = rsqrtf(g_deg[node]);
    int c = min(g_cnt[node], CAP);
    float2 acc = gather_rows<NC>(&g_slot[(long long)node * CAP], c, g_h2h, lane);
    float2 self = __half22float2(*(const __half2*)&g_h2h[(long long)node * NC + lane * 2]);
    float2 o;
    o.x = fmaf(dc, fmaf(dc, self.x, acc.x), __ldg(&b2[lane * 2]));
    o.y = fmaf(dc, fmaf(dc, self.y, acc.y), __ldg(&b2[lane * 2 + 1]));
    *(float2*)&out[(long long)node * NC + lane * 2] = o;
}

extern "C" void kernel_launch(void* const* d_in, const int* in_sizes, int n_in,
                              void* d_out, int out_size) {
    const float* x  = (const float*)d_in[0];
    const int*   ei = (const int*)d_in[1];     // int32 (JAX default x64-disabled)
    const float* ew = (const float*)d_in[2];
    const float* W1 = (const float*)d_in[3];
    const float* b1 = (const float*)d_in[4];
    const float* W2 = (const float*)d_in[5];
    const float* b2 = (const float*)d_in[6];
    float* out = (float*)d_out;

    (void)in_sizes; (void)n_in; (void)out_size;

    static cudaStream_t s2 = nullptr;
    static cudaEvent_t eFork = nullptr, eJoin = nullptr;
    if (s2 == nullptr) {
        cudaStreamCreateWithFlags(&s2, cudaStreamNonBlocking);
        cudaEventCreateWithFlags(&eFork, cudaEventDisableTiming);
        cudaEventCreateWithFlags(&eJoin, cudaEventDisableTiming);
    }

    // Fork: gemm1 (x,W1 only) runs concurrently with edge preprocessing.
    cudaEventRecord(eFork, 0);
    cudaStreamWaitEvent(s2, eFork, 0);
    gemm1<<<(NN + 63) / 64, 256, 0, s2>>>(x, W1);
    cudaEventRecord(eJoin, s2);

    k_init<<<(NN + 255) / 256, 256>>>();
    k_deg<<<(NE + 255) / 256, 256>>>(ei, ew);
    k_place<<<(NE + 255) / 256, 256>>>(ei, ew);

    // Join: fused gather1+gemm2 needs both gemm1 (h1) and k_place (slots).
    cudaStreamWaitEvent(0, eJoin, 0);
    g1g2<<<(NN + 63) / 64, 256>>>(b1, W2);
    gather2<<<(NN + 7) / 8, 256>>>(b2, out);
}